// round 4
// baseline (speedup 1.0000x reference)
#include <cuda_runtime.h>
#include <cstdint>

// ---------------------------------------------------------------------------
// S4D kernel materialization:
//   K[d,l] = 2*Re( sum_n Cc[d,n] * exp(dtA[d,n] * l) ),  D=512, N=32, L=8192
//
// Round 4: single fused kernel, one balanced wave of 592 blocks = 148 SMs x
// 4 CTAs. Recurrence coefficients live in SHARED memory (reloaded per emit
// with volatile LDS) so per-thread registers fit 128 -> 16 warps/SM instead
// of 12. Each block discretizes its (<=2) d's coefficient tables into smem
// in the prologue (precompute fused, one launch total).
//
//   x_n(l) = Re(u_n * r_n^l) satisfies the stable 2-term real recurrence
//       x_{k+1} = 2Re(r^T) x_k - |r^T|^2 x_{k-1}   (stride-T sampling)
//   advanced with packed fma.rn.f32x2.
// ---------------------------------------------------------------------------

#define D_MODEL 512
#define NSTATE  32
#define SEQ     8192
#define TSTRIDE 148                    // 512*148 = 75776 = 592 blocks * 128
#define MAIN_BLOCKS 592                // = 148 SMs * 4 CTAs, one wave
#define MAIN_THREADS 128
// 8192 = 55*148 + 52:  t < 52 -> 56 emits, else 55.

typedef unsigned long long u64;

// ---- packed f32x2 helpers --------------------------------------------------
__device__ __forceinline__ u64 pack2(float lo, float hi) {
    u64 r; asm("mov.b64 %0, {%1, %2};" : "=l"(r) : "f"(lo), "f"(hi)); return r;
}
__device__ __forceinline__ void unpack2(u64 v, float& lo, float& hi) {
    asm("mov.b64 {%0, %1}, %2;" : "=f"(lo), "=f"(hi) : "l"(v));
}
__device__ __forceinline__ u64 add2(u64 a, u64 b) {
    u64 d; asm("add.rn.f32x2 %0, %1, %2;" : "=l"(d) : "l"(a), "l"(b)); return d;
}
__device__ __forceinline__ u64 mul2(u64 a, u64 b) {
    u64 d; asm("mul.rn.f32x2 %0, %1, %2;" : "=l"(d) : "l"(a), "l"(b)); return d;
}
__device__ __forceinline__ u64 fma2(u64 a, u64 b, u64 c) {
    u64 d; asm("fma.rn.f32x2 %0, %1, %2, %3;" : "=l"(d) : "l"(a), "l"(b), "l"(c)); return d;
}

// Volatile v4 shared load of one coefficient pack: {a2_lo, a2_hi, mn_lo, mn_hi}.
// Volatile so ptxas cannot hoist these out of the loop back into registers.
__device__ __forceinline__ void lds_coef(uint32_t saddr, u64& a2p, u64& mnp) {
    float x, y, z, w;
    asm volatile("ld.volatile.shared.v4.f32 {%0,%1,%2,%3}, [%4];"
                 : "=f"(x), "=f"(y), "=f"(z), "=f"(w) : "r"(saddr));
    a2p = pack2(x, y);
    mnp = pack2(z, w);
}

// Depth-4 tree reduction of 16 packs -> scalar (15 add2 + 1 fadd).
__device__ __forceinline__ float reduce16(const u64* X)
{
    u64 a0 = add2(X[0],  X[1]);
    u64 a1 = add2(X[2],  X[3]);
    u64 a2 = add2(X[4],  X[5]);
    u64 a3 = add2(X[6],  X[7]);
    u64 a4 = add2(X[8],  X[9]);
    u64 a5 = add2(X[10], X[11]);
    u64 a6 = add2(X[12], X[13]);
    u64 a7 = add2(X[14], X[15]);
    u64 b0 = add2(a0, a1);
    u64 b1 = add2(a2, a3);
    u64 b2 = add2(a4, a5);
    u64 b3 = add2(a6, a7);
    u64 c0 = add2(b0, b1);
    u64 c1 = add2(b2, b3);
    u64 d0 = add2(c0, c1);
    float lo, hi;
    unpack2(d0, lo, hi);
    return lo + hi;
}

// ---------------------------------------------------------------------------
// Fused kernel. Block b covers g in [128b, 128b+128) -> at most 2 distinct d
// (since 128 < TSTRIDE). Prologue: 64 threads discretize the two d's
// coefficient tables into smem. Mainloop: 2-term real recurrence, coefs
// streamed from smem each emit.
// ---------------------------------------------------------------------------
__global__ void __launch_bounds__(MAIN_THREADS, 4)
s4d_fused_kernel(const float* __restrict__ log_dt,
                 const float* __restrict__ log_A_real,
                 const float* __restrict__ A_imag,
                 const float2* __restrict__ C,
                 float* __restrict__ out)
{
    __shared__ float4 sInit[2][NSTATE];      // {dtAr, dtAi, Ccr, Cci}
    __shared__ float2 sRT  [2][NSTATE];      // r^T
    __shared__ float4 sCoef[2][NSTATE / 2];  // {a2_lo, a2_hi, mn_lo, mn_hi}

    unsigned tid = threadIdx.x;
    unsigned g   = blockIdx.x * MAIN_THREADS + tid;
    unsigned d0  = (blockIdx.x * MAIN_THREADS) / TSTRIDE;

    // ---- Prologue: discretization for d0 and d0+1 (64 threads) -------------
    if (tid < 2 * NSTATE) {
        unsigned dd = tid >> 5;          // 0 or 1
        unsigned n  = tid & 31;
        unsigned d  = d0 + dd;
        if (d < D_MODEL) {
            int i = (int)(d * NSTATE + n);
            float dt   = expf(log_dt[d]);
            float Ar   = -expf(log_A_real[i]);
            float Ai   = A_imag[i];
            float dtAr = Ar * dt;
            float dtAi = Ai * dt;

            // E = exp(dtA) - 1
            float er = expf(dtAr);
            float s, c;
            sincosf(dtAi, &s, &c);
            float Er = er * c - 1.0f;
            float Ei = er * s;

            // q = E / (A + 1e-8)
            float ar8 = Ar + 1e-8f;
            float inv = 1.0f / (ar8 * ar8 + Ai * Ai);
            float qr = (Er * ar8 + Ei * Ai) * inv;
            float qi = (Ei * ar8 - Er * Ai) * inv;

            // Cc = 2 * C * q
            float2 Cv = C[i];
            float Ccr = 2.0f * (Cv.x * qr - Cv.y * qi);
            float Cci = 2.0f * (Cv.x * qi + Cv.y * qr);

            // r^T = exp(dtA * T)
            float eT = expf(dtAr * (float)TSTRIDE);
            float sT, cT;
            sincosf(dtAi * (float)TSTRIDE, &sT, &cT);
            float rtx = eT * cT, rty = eT * sT;

            sInit[dd][n] = make_float4(dtAr, dtAi, Ccr, Cci);
            sRT[dd][n]   = make_float2(rtx, rty);
            float* cf = (float*)&sCoef[dd][n >> 1];
            cf[(n & 1)]     = rtx + rtx;                    // a2
            cf[2 + (n & 1)] = -(rtx * rtx + rty * rty);     // mn
        }
    }
    __syncthreads();

    // ---- Per-thread state init --------------------------------------------
    unsigned d  = g / TSTRIDE;
    unsigned t  = g - d * TSTRIDE;
    unsigned dd = d - d0;
    float ft = (float)t;

    u64 XA[16], XB[16];

#pragma unroll
    for (int j = 0; j < 16; j++) {
        float xa[2], xb[2];
#pragma unroll
        for (int h = 0; h < 2; h++) {
            int n = 2 * j + h;
            float4 ini = sInit[dd][n];
            float2 rt  = sRT[dd][n];
            float e = __expf(ini.x * ft);
            float s, c;
            __sincosf(ini.y * ft, &s, &c);
            float wr = e * c, wi = e * s;             // exp(dtA * t)
            float ur = ini.z * wr - ini.w * wi;       // u = Cc * exp(dtA*t)
            float ui = ini.z * wi + ini.w * wr;
            xa[h] = ur;                                // x(t)
            xb[h] = ur * rt.x - ui * rt.y;             // x(t+T)
        }
        XA[j] = pack2(xa[0], xa[1]);
        XB[j] = pack2(xb[0], xb[1]);
    }

    uint32_t cbase = (uint32_t)__cvta_generic_to_shared(&sCoef[dd][0]);
    float* op = out + (size_t)d * SEQ + t;

    // ---- Mainloop: 27 iterations x 2 emits = emits 0..53 (always in bounds:
    // max l = t + 53*148 = 147 + 7844 = 7991 < 8192) ------------------------
#pragma unroll 1
    for (int k = 0; k < 27; k++) {
        // emit 2k (held in XA)
        op[0] = reduce16(XA);
        op += TSTRIDE;
        // XA <- a2*XB + mn*XA
#pragma unroll
        for (int j = 0; j < 16; j++) {
            u64 a2p, mnp;
            lds_coef(cbase + 16u * j, a2p, mnp);
            XA[j] = fma2(a2p, XB[j], mul2(mnp, XA[j]));
        }
        // emit 2k+1 (held in XB)
        op[0] = reduce16(XB);
        op += TSTRIDE;
        // XB <- a2*XA + mn*XB
#pragma unroll
        for (int j = 0; j < 16; j++) {
            u64 a2p, mnp;
            lds_coef(cbase + 16u * j, a2p, mnp);
            XB[j] = fma2(a2p, XA[j], mul2(mnp, XB[j]));
        }
    }

    // ---- Tail: emit 54 (l = t + 7992 <= 8139, always valid),
    //            emit 55 (l = t + 8140, valid iff t < 52) -------------------
    op[0] = reduce16(XA);
    if (t < 52u) op[TSTRIDE] = reduce16(XB);
}

// ---------------------------------------------------------------------------
extern "C" void kernel_launch(void* const* d_in, const int* in_sizes, int n_in,
                              void* d_out, int out_size)
{
    const float*  log_dt     = (const float*)d_in[0];
    const float*  log_A_real = (const float*)d_in[1];
    const float*  A_imag     = (const float*)d_in[2];
    const float2* C          = (const float2*)d_in[3];
    float* out = (float*)d_out;

    s4d_fused_kernel<<<MAIN_BLOCKS, MAIN_THREADS>>>(
        log_dt, log_A_real, A_imag, C, out);
}

// round 6
// speedup vs baseline: 1.5185x; 1.5185x over previous
#include <cuda_runtime.h>
#include <cuda_bf16.h>
#include <mma.h>
#include <cstdint>

using namespace nvcuda;

// ---------------------------------------------------------------------------
// S4D kernel materialization via WMMA bf16 tensor cores (HMMA, sm_100-safe).
//   K[d,l] = 2*Re( sum_n Cc[d,n] * exp(dtA[d,n] * l) ),  D=512, N=32, L=8192
//
// Split l = 64*m + b (m in [0,128), b in [0,64)):
//   K[d, 64m+b] = sum_k A[m,k] * B[b,k]       (real GEMM, Kdim = 64)
//   A[m, n]    = Re(u),  A[m, 32+n] = Im(u),  u = 2*Cc_n * (r_n^64)^m
//   B[b, n]    = Re(w),  B[b, 32+n] = -Im(w), w = r_n^b,  r_n = exp(dtA_n)
// so sum_k A[m,k]B[b,k] = Re(2*Cc_n * r_n^(64m+b)) summed over n.   ✓
//
// One CTA per d: build A,B in smem as bf16 hi/lo split; run
// D = Ah*Bh + Ah*Bl + Al*Bh  (3 passes, f32 accumulate) on wmma 16x16x16.
// ---------------------------------------------------------------------------

#define D_MODEL 512
#define SEQ     8192
#define NST     32
#define LDAB    72                    // bf16 elements per smem row (144 B, 16B-mult)

// Dynamic smem layout (bytes)
#define OFF_AH   0                    // 128 x 72 bf16 = 18432
#define OFF_AL   18432
#define OFF_BH   36864                // 64 x 72 bf16 = 9216
#define OFF_BL   46080
#define OFF_TBL  55296                // float2 [24][34] = 6528
#define TROW     34
#define SMEM_TOTAL 61824

// ---- helpers ---------------------------------------------------------------
__device__ __forceinline__ float2 cmul(float2 a, float2 b) {
    return make_float2(a.x * b.x - a.y * b.y, a.x * b.y + a.y * b.x);
}
// pack two floats -> bf16x2 (lo value in low 16 bits = lower address)
__device__ __forceinline__ uint32_t pkbf2(float lo, float hi) {
    uint32_t r;
    asm("cvt.rn.bf16x2.f32 %0, %1, %2;" : "=r"(r) : "f"(hi), "f"(lo));
    return r;
}
__device__ __forceinline__ float lo_of(uint32_t p) { return __uint_as_float(p << 16); }
__device__ __forceinline__ float hi_of(uint32_t p) { return __uint_as_float(p & 0xFFFF0000u); }

// ---------------------------------------------------------------------------
__global__ void __launch_bounds__(128, 3)
s4d_wmma_kernel(const float* __restrict__ log_dt,
                const float* __restrict__ log_A_real,
                const float* __restrict__ A_imag,
                const float2* __restrict__ C,
                float* __restrict__ out)
{
    extern __shared__ char dsm[];
    float2* tbl = (float2*)(dsm + OFF_TBL);
    uint32_t* ah32 = (uint32_t*)(dsm + OFF_AH);   // 36 u32 per row
    uint32_t* al32 = (uint32_t*)(dsm + OFF_AL);
    uint32_t* bh32 = (uint32_t*)(dsm + OFF_BH);
    uint32_t* bl32 = (uint32_t*)(dsm + OFF_BL);

    const int d    = blockIdx.x;
    const int tid  = threadIdx.x;
    const int wid  = tid >> 5;

    // ---- Phase 1: per-state discretization + r power tables ----------------
    float2 r8v = make_float2(1.f, 0.f);
    float2 Cc  = make_float2(0.f, 0.f);
    if (tid < NST) {
        int n = tid;
        int i = d * NST + n;
        float dt   = expf(log_dt[d]);
        float Ar   = -expf(log_A_real[i]);
        float Ai   = A_imag[i];
        float dtAr = Ar * dt;
        float dtAi = Ai * dt;
        float er = expf(dtAr);
        float s, c;
        sincosf(dtAi, &s, &c);
        float2 r = make_float2(er * c, er * s);

        // discretized C with the final 2x folded in
        float Er = er * c - 1.0f, Ei = er * s;
        float ar8 = Ar + 1e-8f;
        float inv = 1.0f / (ar8 * ar8 + Ai * Ai);
        float qr = (Er * ar8 + Ei * Ai) * inv;
        float qi = (Ei * ar8 - Er * Ai) * inv;
        float2 Cv = C[i];
        Cc = make_float2(2.0f * (Cv.x * qr - Cv.y * qi),
                         2.0f * (Cv.x * qi + Cv.y * qr));

        // rows 0..7:  r^i ;  rows 8..15: (r^8)^j
        float2 p = make_float2(1.f, 0.f);
        tbl[0 * TROW + n] = p;
#pragma unroll
        for (int k = 1; k < 8; k++) { p = cmul(p, r); tbl[k * TROW + n] = p; }
        r8v = cmul(p, r);                        // r^8
        p = make_float2(1.f, 0.f);
        tbl[8 * TROW + n] = p;
#pragma unroll
        for (int k = 1; k < 8; k++) { p = cmul(p, r8v); tbl[(8 + k) * TROW + n] = p; }
    }
    __syncthreads();

    // ---- Phase 2: B operand rows (b = tid < 64) ----------------------------
    if (tid < 64) {
        int b = tid;
        const float4* ra = (const float4*)(tbl + (b & 7) * TROW);
        const float4* rb = (const float4*)(tbl + (8 + (b >> 3)) * TROW);
#pragma unroll
        for (int n2 = 0; n2 < 16; n2++) {
            float4 a = ra[n2], q = rb[n2];
            float2 w0 = cmul(make_float2(a.x, a.y), make_float2(q.x, q.y));
            float2 w1 = cmul(make_float2(a.z, a.w), make_float2(q.z, q.w));
            float br0 = w0.x,  br1 = w1.x;
            float bi0 = -w0.y, bi1 = -w1.y;      // B carries -Im(w)
            uint32_t ph = pkbf2(br0, br1);
            bh32[b * 36 + n2] = ph;
            bl32[b * 36 + n2] = pkbf2(br0 - lo_of(ph), br1 - hi_of(ph));
            ph = pkbf2(bi0, bi1);
            bh32[b * 36 + 16 + n2] = ph;
            bl32[b * 36 + 16 + n2] = pkbf2(bi0 - lo_of(ph), bi1 - hi_of(ph));
        }
    }
    __syncthreads();

    // ---- Phase 3: Q power tables (overwrite tbl) ---------------------------
    if (tid < NST) {
        int n = tid;
        float2 r64 = cmul(r8v, r8v);             // r^16
        r64 = cmul(r64, r64);                    // r^32
        r64 = cmul(r64, r64);                    // r^64
        // rows 0..7: r64^i ; rows 8..23: Cc * (r64^8)^j
        float2 p = make_float2(1.f, 0.f);
        tbl[0 * TROW + n] = p;
#pragma unroll
        for (int k = 1; k < 8; k++) { p = cmul(p, r64); tbl[k * TROW + n] = p; }
        float2 q8 = cmul(p, r64);                // r64^8
        p = Cc;
        tbl[8 * TROW + n] = p;
#pragma unroll
        for (int k = 1; k < 16; k++) { p = cmul(p, q8); tbl[(8 + k) * TROW + n] = p; }
    }
    __syncthreads();

    // ---- Phase 4: A operand rows (m = tid) ---------------------------------
    {
        int m = tid;
        const float4* ra = (const float4*)(tbl + (m & 7) * TROW);
        const float4* rb = (const float4*)(tbl + (8 + (m >> 3)) * TROW);
#pragma unroll
        for (int n2 = 0; n2 < 16; n2++) {
            float4 a = ra[n2], q = rb[n2];
            float2 u0 = cmul(make_float2(a.x, a.y), make_float2(q.x, q.y));
            float2 u1 = cmul(make_float2(a.z, a.w), make_float2(q.z, q.w));
            uint32_t ph = pkbf2(u0.x, u1.x);
            ah32[m * 36 + n2] = ph;
            al32[m * 36 + n2] = pkbf2(u0.x - lo_of(ph), u1.x - hi_of(ph));
            ph = pkbf2(u0.y, u1.y);
            ah32[m * 36 + 16 + n2] = ph;
            al32[m * 36 + 16 + n2] = pkbf2(u0.y - lo_of(ph), u1.y - hi_of(ph));
        }
    }
    __syncthreads();

    // ---- Phase 5: WMMA. Warp w owns M-tiles {2w, 2w+1} x N-tiles {0..3} ----
    {
        const __nv_bfloat16* Ah = (const __nv_bfloat16*)(dsm + OFF_AH);
        const __nv_bfloat16* Al = (const __nv_bfloat16*)(dsm + OFF_AL);
        const __nv_bfloat16* Bh = (const __nv_bfloat16*)(dsm + OFF_BH);
        const __nv_bfloat16* Bl = (const __nv_bfloat16*)(dsm + OFF_BL);

        wmma::fragment<wmma::accumulator, 16, 16, 16, float> acc[2][4];
#pragma unroll
        for (int i = 0; i < 2; i++)
#pragma unroll
            for (int j = 0; j < 4; j++) wmma::fill_fragment(acc[i][j], 0.0f);

#pragma unroll
        for (int pass = 0; pass < 3; pass++) {
            const __nv_bfloat16* Abuf = (pass == 2) ? Al : Ah;
            const __nv_bfloat16* Bbuf = (pass == 1) ? Bl : Bh;
#pragma unroll
            for (int k = 0; k < 4; k++) {
                wmma::fragment<wmma::matrix_a, 16, 16, 16, __nv_bfloat16,
                               wmma::row_major> af[2];
                wmma::fragment<wmma::matrix_b, 16, 16, 16, __nv_bfloat16,
                               wmma::col_major> bf[4];
#pragma unroll
                for (int i = 0; i < 2; i++)
                    wmma::load_matrix_sync(
                        af[i], Abuf + (wid * 2 + i) * 16 * LDAB + k * 16, LDAB);
#pragma unroll
                for (int j = 0; j < 4; j++)
                    wmma::load_matrix_sync(
                        bf[j], Bbuf + j * 16 * LDAB + k * 16, LDAB);
#pragma unroll
                for (int i = 0; i < 2; i++)
#pragma unroll
                    for (int j = 0; j < 4; j++)
                        wmma::mma_sync(acc[i][j], af[i], bf[j], acc[i][j]);
            }
        }

        // ---- epilogue: D[m,b] -> out[d*8192 + m*64 + b] --------------------
        float* od = out + (size_t)d * SEQ;
#pragma unroll
        for (int i = 0; i < 2; i++)
#pragma unroll
            for (int j = 0; j < 4; j++)
                wmma::store_matrix_sync(
                    od + (wid * 2 + i) * 16 * 64 + j * 16, acc[i][j], 64,
                    wmma::mem_row_major);
    }
}

// ---------------------------------------------------------------------------
extern "C" void kernel_launch(void* const* d_in, const int* in_sizes, int n_in,
                              void* d_out, int out_size)
{
    const float*  log_dt     = (const float*)d_in[0];
    const float*  log_A_real = (const float*)d_in[1];
    const float*  A_imag     = (const float*)d_in[2];
    const float2* C          = (const float2*)d_in[3];
    float* out = (float*)d_out;

    static bool attr_set = false;
    if (!attr_set) {
        cudaFuncSetAttribute(s4d_wmma_kernel,
                             cudaFuncAttributeMaxDynamicSharedMemorySize,
                             SMEM_TOTAL);
        attr_set = true;
    }
    s4d_wmma_kernel<<<D_MODEL, 128, SMEM_TOTAL>>>(
        log_dt, log_A_real, A_imag, C, out);
}

// round 7
// speedup vs baseline: 1.9872x; 1.3087x over previous
#include <cuda_runtime.h>
#include <cuda_fp16.h>
#include <mma.h>
#include <cstdint>

using namespace nvcuda;

// ---------------------------------------------------------------------------
// S4D kernel materialization via WMMA fp16 tensor cores (HMMA, sm_100-safe).
//   K[d,l] = 2*Re( sum_n Cc[d,n] * exp(dtA[d,n] * l) ),  D=512, N=32, L=8192
//
// Split l = 64*m + b (m in [0,128), b in [0,64)):
//   K[d, 64m+b] = sum_k A[m,k] * B[b,k]       (real GEMM, Kdim = 64)
//   A[m, n]    = Re(u),  A[m, 32+n] = Im(u),  u = 2*Cc_n * (r_n^64)^m
//   B[b, n]    = Re(w),  B[b, 32+n] = -Im(w), w = r_n^b,  r_n = exp(dtA_n)
//
// fp16 operands: A split hi/lo (2-pass: Ah*B + Al*B, f32 accumulate),
// B single fp16 (residual ~2^-12 -> global rel_err ~1e-4, gate is 1e-3).
// smem 52.6 KB + regs<=128  ->  4 CTAs/SM  ->  single 512-CTA wave.
// ---------------------------------------------------------------------------

#define D_MODEL 512
#define SEQ     8192
#define NST     32
#define LDAB    72                    // fp16 elems per smem row (144 B)

// Dynamic smem layout (bytes)
#define OFF_AH   0                    // 128 x 144 = 18432
#define OFF_AL   18432                // 18432
#define OFF_BH   36864                // 64 x 144 = 9216
#define OFF_TBL  46080                // float2 [24][34] = 6528
#define TROW     34
#define SMEM_TOTAL 52608

// ---- helpers ---------------------------------------------------------------
__device__ __forceinline__ float2 cmul(float2 a, float2 b) {
    return make_float2(a.x * b.x - a.y * b.y, a.x * b.y + a.y * b.x);
}
// exp(mr + i*mi) with 2-term mod-2pi reduction (safe for |mi| up to ~1e3)
__device__ __forceinline__ float2 cexp_red(float mr, float mi) {
    float e = __expf(mr);
    float k = rintf(mi * 0.15915494f);
    float th = fmaf(-k, 6.2831855f, mi);        // 2pi hi
    th = fmaf(k, 1.7484556e-7f, th);            // 2pi lo correction
    float s, c;
    __sincosf(th, &s, &c);
    return make_float2(e * c, e * s);
}
// pack two fp32 -> half2 (v0 in low half = lower address)
__device__ __forceinline__ uint32_t pkh2(float v0, float v1) {
    __half2 h = __halves2half2(__float2half_rn(v0), __float2half_rn(v1));
    return *(uint32_t*)&h;
}

// ---------------------------------------------------------------------------
__global__ void __launch_bounds__(128, 4)
s4d_wmma_kernel(const float* __restrict__ log_dt,
                const float* __restrict__ log_A_real,
                const float* __restrict__ A_imag,
                const float2* __restrict__ C,
                float* __restrict__ out)
{
    extern __shared__ char dsm[];
    float2*   tbl  = (float2*)(dsm + OFF_TBL);
    uint32_t* ah32 = (uint32_t*)(dsm + OFF_AH);   // 36 u32 per row
    uint32_t* al32 = (uint32_t*)(dsm + OFF_AL);
    uint32_t* bh32 = (uint32_t*)(dsm + OFF_BH);

    const int d   = blockIdx.x;
    const int tid = threadIdx.x;
    const int wid = tid >> 5;

    // ---- Phase 1: R power tables, chains split across warps 0 and 1 --------
    // warp0: rows 0..7 = r^i ; warp1: rows 8..15 = (r^8)^j  (r^8 direct exp)
    if (tid < 64) {
        int n = tid & 31;
        int i = d * NST + n;
        float dt   = expf(log_dt[d]);
        float dtAr = -expf(log_A_real[i]) * dt;
        float dtAi = A_imag[i] * dt;
        if (tid < 32) {
            float2 r = cexp_red(dtAr, dtAi);
            float2 p = make_float2(1.f, 0.f);
            tbl[0 * TROW + n] = p;
#pragma unroll
            for (int k = 1; k < 8; k++) { p = cmul(p, r); tbl[k * TROW + n] = p; }
        } else {
            float2 r8 = cexp_red(8.f * dtAr, 8.f * dtAi);
            float2 p = make_float2(1.f, 0.f);
            tbl[8 * TROW + n] = p;
#pragma unroll
            for (int k = 1; k < 8; k++) { p = cmul(p, r8); tbl[(8 + k) * TROW + n] = p; }
        }
    }
    __syncthreads();

    // ---- Phase 2: B rows (b = tid < 64), single fp16 ------------------------
    if (tid < 64) {
        int b = tid;
        const float4* ra = (const float4*)(tbl + (b & 7) * TROW);
        const float4* rb = (const float4*)(tbl + (8 + (b >> 3)) * TROW);
#pragma unroll
        for (int n2 = 0; n2 < 16; n2++) {
            float4 a = ra[n2], q = rb[n2];
            float2 w0 = cmul(make_float2(a.x, a.y), make_float2(q.x, q.y));
            float2 w1 = cmul(make_float2(a.z, a.w), make_float2(q.z, q.w));
            bh32[b * 36 + n2]      = pkh2(w0.x, w1.x);    // Re
            bh32[b * 36 + 16 + n2] = pkh2(-w0.y, -w1.y);  // -Im
        }
    }
    __syncthreads();

    // ---- Phase 3: Q tables overwrite tbl, chains split across warps --------
    // warp0: rows 0..7 = r64^i ; warp1: rows 8..23 = Cc * (r64^8)^j
    if (tid < 64) {
        int n = tid & 31;
        int i = d * NST + n;
        float dt   = expf(log_dt[d]);
        float Ar   = -expf(log_A_real[i]);
        float Ai   = A_imag[i];
        float dtAr = Ar * dt;
        float dtAi = Ai * dt;
        if (tid < 32) {
            float2 r64 = cexp_red(64.f * dtAr, 64.f * dtAi);
            float2 p = make_float2(1.f, 0.f);
            tbl[0 * TROW + n] = p;
#pragma unroll
            for (int k = 1; k < 8; k++) { p = cmul(p, r64); tbl[k * TROW + n] = p; }
        } else {
            // discretized C with the final 2x folded in (precise path)
            float er = expf(dtAr);
            float s, c;
            sincosf(dtAi, &s, &c);
            float Er = er * c - 1.0f, Ei = er * s;
            float ar8 = Ar + 1e-8f;
            float inv = 1.0f / (ar8 * ar8 + Ai * Ai);
            float qr = (Er * ar8 + Ei * Ai) * inv;
            float qi = (Ei * ar8 - Er * Ai) * inv;
            float2 Cv = C[i];
            float2 Cc = make_float2(2.0f * (Cv.x * qr - Cv.y * qi),
                                    2.0f * (Cv.x * qi + Cv.y * qr));
            float2 q8 = cexp_red(512.f * dtAr, 512.f * dtAi);   // r^512
            float2 p = Cc;
            tbl[8 * TROW + n] = p;
#pragma unroll
            for (int k = 1; k < 16; k++) { p = cmul(p, q8); tbl[(8 + k) * TROW + n] = p; }
        }
    }
    __syncthreads();

    // ---- Phase 4: A rows (m = tid), fp16 hi/lo split ------------------------
    {
        int m = tid;
        const float4* ra = (const float4*)(tbl + (m & 7) * TROW);
        const float4* rb = (const float4*)(tbl + (8 + (m >> 3)) * TROW);
#pragma unroll
        for (int n2 = 0; n2 < 16; n2++) {
            float4 a = ra[n2], q = rb[n2];
            float2 u0 = cmul(make_float2(a.x, a.y), make_float2(q.x, q.y));
            float2 u1 = cmul(make_float2(a.z, a.w), make_float2(q.z, q.w));
            // real parts
            __half h0 = __float2half_rn(u0.x), h1 = __float2half_rn(u1.x);
            ah32[m * 36 + n2] = pkh2(u0.x, u1.x);
            al32[m * 36 + n2] = pkh2(u0.x - __half2float(h0),
                                     u1.x - __half2float(h1));
            // imag parts
            h0 = __float2half_rn(u0.y); h1 = __float2half_rn(u1.y);
            ah32[m * 36 + 16 + n2] = pkh2(u0.y, u1.y);
            al32[m * 36 + 16 + n2] = pkh2(u0.y - __half2float(h0),
                                          u1.y - __half2float(h1));
        }
    }
    __syncthreads();

    // ---- Phase 5: WMMA (2 passes). Warp w: M-tiles {2w,2w+1} x N-tiles 0..3 -
    {
        const __half* Ah = (const __half*)(dsm + OFF_AH);
        const __half* Al = (const __half*)(dsm + OFF_AL);
        const __half* Bh = (const __half*)(dsm + OFF_BH);

        wmma::fragment<wmma::accumulator, 16, 16, 16, float> acc[2][4];
#pragma unroll
        for (int i = 0; i < 2; i++)
#pragma unroll
            for (int j = 0; j < 4; j++) wmma::fill_fragment(acc[i][j], 0.0f);

#pragma unroll
        for (int pass = 0; pass < 2; pass++) {
            const __half* Abuf = pass ? Al : Ah;
#pragma unroll
            for (int k = 0; k < 4; k++) {
                wmma::fragment<wmma::matrix_a, 16, 16, 16, __half,
                               wmma::row_major> af[2];
                wmma::fragment<wmma::matrix_b, 16, 16, 16, __half,
                               wmma::col_major> bf[4];
#pragma unroll
                for (int i = 0; i < 2; i++)
                    wmma::load_matrix_sync(
                        af[i], Abuf + (wid * 2 + i) * 16 * LDAB + k * 16, LDAB);
#pragma unroll
                for (int j = 0; j < 4; j++)
                    wmma::load_matrix_sync(
                        bf[j], Bh + j * 16 * LDAB + k * 16, LDAB);
#pragma unroll
                for (int i = 0; i < 2; i++)
#pragma unroll
                    for (int j = 0; j < 4; j++)
                        wmma::mma_sync(acc[i][j], af[i], bf[j], acc[i][j]);
            }
        }

        // ---- epilogue: D[m,b] -> out[d*8192 + m*64 + b] --------------------
        float* od = out + (size_t)d * SEQ;
#pragma unroll
        for (int i = 0; i < 2; i++)
#pragma unroll
            for (int j = 0; j < 4; j++)
                wmma::store_matrix_sync(
                    od + (wid * 2 + i) * 16 * 64 + j * 16, acc[i][j], 64,
                    wmma::mem_row_major);
    }
}

// ---------------------------------------------------------------------------
extern "C" void kernel_launch(void* const* d_in, const int* in_sizes, int n_in,
                              void* d_out, int out_size)
{
    const float*  log_dt     = (const float*)d_in[0];
    const float*  log_A_real = (const float*)d_in[1];
    const float*  A_imag     = (const float*)d_in[2];
    const float2* C          = (const float2*)d_in[3];
    float* out = (float*)d_out;

    static bool attr_set = false;
    if (!attr_set) {
        cudaFuncSetAttribute(s4d_wmma_kernel,
                             cudaFuncAttributeMaxDynamicSharedMemorySize,
                             SMEM_TOTAL);
        attr_set = true;
    }
    s4d_wmma_kernel<<<D_MODEL, 128, SMEM_TOTAL>>>(
        log_dt, log_A_real, A_imag, C, out);
}